// round 11
// baseline (speedup 1.0000x reference)
#include <cuda_runtime.h>

// NeuS render: pixel/invdepth/weight from sdf+color+z_vals.
// Telescoping identity: trans[i] = sig[i]/sig[0], so
//   weight[i] = max(sig[i]-sig[i+1], 0) / sig[0], weight[0]=weight[S-1]=0.
// Background fold: pixel = bg + sum_i w[i]*(c[i]-bg).
// One warp per ray; 4 samples per lane. Evict-first loads; write-through
// weight store. launch_bounds(256,7) caps regs at 36 -> 1792 threads/SM for
// more in-flight loads (DRAM utilization, not latency, is the binder).
// Output layout: pixel[R*3] | invdepth[R] | weight[R*S].

#define N_RAYS    65536
#define N_SAMPLES 128

__global__ __launch_bounds__(256, 7)
void neus_render_kernel(const float* __restrict__ sdf,
                        const float* __restrict__ color,
                        const float* __restrict__ z_vals,
                        const float* __restrict__ s_ptr,
                        const float* __restrict__ bg,
                        float* __restrict__ out)
{
    const int warp_id = (blockIdx.x * blockDim.x + threadIdx.x) >> 5;
    const int lane    = threadIdx.x & 31;

    const float s   = __ldg(s_ptr);
    const float bgr = __ldg(bg + 0);
    const float bgg = __ldg(bg + 1);
    const float bgb = __ldg(bg + 2);

    const size_t ray = (size_t)warp_id;
    const float4* sdf4 = (const float4*)(sdf + ray * N_SAMPLES) + lane;
    const float4* z4   = (const float4*)(z_vals + ray * N_SAMPLES) + lane;
    const float4* c4   = (const float4*)(color + ray * (size_t)(N_SAMPLES * 3)) + lane * 3;

    // ---- streaming loads, front-batched (MLP_p1 = 5) ----
    const float4 sd = __ldcs(sdf4);
    const float4 zz = __ldcs(z4);
    const float4 c0 = __ldcs(c4 + 0);   // s0.r s0.g s0.b s1.r
    const float4 c1 = __ldcs(c4 + 1);   // s1.g s1.b s2.r s2.g
    const float4 c2 = __ldcs(c4 + 2);   // s2.b s3.r s3.g s3.b

    // ---- sigmoids for this lane's 4 samples ----
    const float sigA = 1.0f / (1.0f + __expf(-sd.x * s));
    const float sigB = 1.0f / (1.0f + __expf(-sd.y * s));
    const float sigC = 1.0f / (1.0f + __expf(-sd.z * s));
    const float sigD = 1.0f / (1.0f + __expf(-sd.w * s));

    // neighbor's first sigmoid (sample 4*lane+4); lane 31's is unused
    const float sigNext = __shfl_down_sync(0xffffffffu, sigA, 1);
    // ray's first sigmoid (sample 0)
    const float sig0    = __shfl_sync(0xffffffffu, sigA, 0);
    const float inv0    = 1.0f / sig0;

    // ---- weights: w[i] = max(sig[i]-sig[i+1], 0) / sig[0] ----
    float4 w;
    w.x = (lane == 0)  ? 0.0f : fmaxf(sigA - sigB, 0.0f) * inv0;   // weight[0] = 0
    w.y =                       fmaxf(sigB - sigC, 0.0f) * inv0;
    w.z =                       fmaxf(sigC - sigD, 0.0f) * inv0;
    w.w = (lane == 31) ? 0.0f : fmaxf(sigD - sigNext, 0.0f) * inv0; // weight[S-1] = 0

    // ---- write-through weight store (bypass L2 residency), issued early ----
    float4* wout = (float4*)(out + (size_t)N_RAYS * 4 + ray * N_SAMPLES) + lane;
    __stwt(wout, w);

    // ---- per-lane partial reductions ----
    float invd = __fdividef(w.x, zz.x) + __fdividef(w.y, zz.y)
               + __fdividef(w.z, zz.z) + __fdividef(w.w, zz.w);

    // pixel = bg + sum w*(c - bg): residual-transmittance fold, no wsum needed
    float pr = w.x * (c0.x - bgr) + w.y * (c0.w - bgr) + w.z * (c1.z - bgr) + w.w * (c2.y - bgr);
    float pg = w.x * (c0.y - bgg) + w.y * (c1.x - bgg) + w.z * (c1.w - bgg) + w.w * (c2.z - bgg);
    float pb = w.x * (c0.z - bgb) + w.y * (c1.y - bgb) + w.z * (c2.x - bgb) + w.w * (c2.w - bgb);

    // ---- warp butterfly reduction of 4 scalars ----
    #pragma unroll
    for (int off = 16; off > 0; off >>= 1) {
        pr   += __shfl_xor_sync(0xffffffffu, pr,   off);
        pg   += __shfl_xor_sync(0xffffffffu, pg,   off);
        pb   += __shfl_xor_sync(0xffffffffu, pb,   off);
        invd += __shfl_xor_sync(0xffffffffu, invd, off);
    }

    if (lane == 0) {
        out[ray * 3 + 0] = pr + bgr;
        out[ray * 3 + 1] = pg + bgg;
        out[ray * 3 + 2] = pb + bgb;
        out[(size_t)N_RAYS * 3 + ray] = invd;
    }
}

extern "C" void kernel_launch(void* const* d_in, const int* in_sizes, int n_in,
                              void* d_out, int out_size)
{
    const float* sdf    = (const float*)d_in[0];
    const float* color  = (const float*)d_in[1];
    const float* z_vals = (const float*)d_in[2];
    const float* s      = (const float*)d_in[3];
    const float* bg     = (const float*)d_in[4];
    float* out = (float*)d_out;

    // 256 threads = 8 warps = 8 rays per block
    const int block = 256;
    const int grid  = N_RAYS / 8;
    neus_render_kernel<<<grid, block>>>(sdf, color, z_vals, s, bg, out);
}

// round 12
// speedup vs baseline: 1.0010x; 1.0010x over previous
#include <cuda_runtime.h>

// NeuS render: pixel/invdepth/weight from sdf+color+z_vals.
// Telescoping identity: trans[i] = sig[i]/sig[0], so
//   weight[i] = max(sig[i]-sig[i+1], 0) / sig[0], weight[0]=weight[S-1]=0.
// Background fold: pixel = bg + sum_i w[i]*(c[i]-bg).
// One warp per ray; 4 samples per lane. Evict-first loads; write-through
// weight store. NO min-blocks bound: forcing 32 regs (R11) caused spills
// (L1 50->60%, DRAM 79->68%). Natural 39-reg allocation is the best config.
// block=512 halves CTA count to trim CTA-boundary drain.
// Output layout: pixel[R*3] | invdepth[R] | weight[R*S].

#define N_RAYS    65536
#define N_SAMPLES 128

__global__ __launch_bounds__(512)
void neus_render_kernel(const float* __restrict__ sdf,
                        const float* __restrict__ color,
                        const float* __restrict__ z_vals,
                        const float* __restrict__ s_ptr,
                        const float* __restrict__ bg,
                        float* __restrict__ out)
{
    const int warp_id = (blockIdx.x * blockDim.x + threadIdx.x) >> 5;
    const int lane    = threadIdx.x & 31;

    const float s   = __ldg(s_ptr);
    const float bgr = __ldg(bg + 0);
    const float bgg = __ldg(bg + 1);
    const float bgb = __ldg(bg + 2);

    const size_t ray = (size_t)warp_id;
    const float4* sdf4 = (const float4*)(sdf + ray * N_SAMPLES) + lane;
    const float4* z4   = (const float4*)(z_vals + ray * N_SAMPLES) + lane;
    const float4* c4   = (const float4*)(color + ray * (size_t)(N_SAMPLES * 3)) + lane * 3;

    // ---- streaming loads, front-batched (MLP_p1 = 5) ----
    const float4 sd = __ldcs(sdf4);
    const float4 zz = __ldcs(z4);
    const float4 c0 = __ldcs(c4 + 0);   // s0.r s0.g s0.b s1.r
    const float4 c1 = __ldcs(c4 + 1);   // s1.g s1.b s2.r s2.g
    const float4 c2 = __ldcs(c4 + 2);   // s2.b s3.r s3.g s3.b

    // ---- sigmoids for this lane's 4 samples ----
    const float sigA = 1.0f / (1.0f + __expf(-sd.x * s));
    const float sigB = 1.0f / (1.0f + __expf(-sd.y * s));
    const float sigC = 1.0f / (1.0f + __expf(-sd.z * s));
    const float sigD = 1.0f / (1.0f + __expf(-sd.w * s));

    // neighbor's first sigmoid (sample 4*lane+4); lane 31's is unused
    const float sigNext = __shfl_down_sync(0xffffffffu, sigA, 1);
    // ray's first sigmoid (sample 0)
    const float sig0    = __shfl_sync(0xffffffffu, sigA, 0);
    const float inv0    = 1.0f / sig0;

    // ---- weights: w[i] = max(sig[i]-sig[i+1], 0) / sig[0] ----
    float4 w;
    w.x = (lane == 0)  ? 0.0f : fmaxf(sigA - sigB, 0.0f) * inv0;   // weight[0] = 0
    w.y =                       fmaxf(sigB - sigC, 0.0f) * inv0;
    w.z =                       fmaxf(sigC - sigD, 0.0f) * inv0;
    w.w = (lane == 31) ? 0.0f : fmaxf(sigD - sigNext, 0.0f) * inv0; // weight[S-1] = 0

    // ---- write-through weight store (bypass L2 residency), issued early ----
    float4* wout = (float4*)(out + (size_t)N_RAYS * 4 + ray * N_SAMPLES) + lane;
    __stwt(wout, w);

    // ---- per-lane partial reductions ----
    float invd = __fdividef(w.x, zz.x) + __fdividef(w.y, zz.y)
               + __fdividef(w.z, zz.z) + __fdividef(w.w, zz.w);

    // pixel = bg + sum w*(c - bg): residual-transmittance fold, no wsum needed
    float pr = w.x * (c0.x - bgr) + w.y * (c0.w - bgr) + w.z * (c1.z - bgr) + w.w * (c2.y - bgr);
    float pg = w.x * (c0.y - bgg) + w.y * (c1.x - bgg) + w.z * (c1.w - bgg) + w.w * (c2.z - bgg);
    float pb = w.x * (c0.z - bgb) + w.y * (c1.y - bgb) + w.z * (c2.x - bgb) + w.w * (c2.w - bgb);

    // ---- warp butterfly reduction of 4 scalars ----
    #pragma unroll
    for (int off = 16; off > 0; off >>= 1) {
        pr   += __shfl_xor_sync(0xffffffffu, pr,   off);
        pg   += __shfl_xor_sync(0xffffffffu, pg,   off);
        pb   += __shfl_xor_sync(0xffffffffu, pb,   off);
        invd += __shfl_xor_sync(0xffffffffu, invd, off);
    }

    if (lane == 0) {
        out[ray * 3 + 0] = pr + bgr;
        out[ray * 3 + 1] = pg + bgg;
        out[ray * 3 + 2] = pb + bgb;
        out[(size_t)N_RAYS * 3 + ray] = invd;
    }
}

extern "C" void kernel_launch(void* const* d_in, const int* in_sizes, int n_in,
                              void* d_out, int out_size)
{
    const float* sdf    = (const float*)d_in[0];
    const float* color  = (const float*)d_in[1];
    const float* z_vals = (const float*)d_in[2];
    const float* s      = (const float*)d_in[3];
    const float* bg     = (const float*)d_in[4];
    float* out = (float*)d_out;

    // 512 threads = 16 warps = 16 rays per block
    const int block = 512;
    const int grid  = N_RAYS / 16;
    neus_render_kernel<<<grid, block>>>(sdf, color, z_vals, s, bg, out);
}